// round 6
// baseline (speedup 1.0000x reference)
#include <cuda_runtime.h>
#include <math.h>
#include <stdint.h>

// ---------------- problem constants (fixed by setup_inputs) ----------------
#define BB   8
#define LQ   3072
#define CC   768
#define LIN  4096          // 64*64 feature tokens
#define HL   64
#define WL   64
#define NH   6
#define NP   4
#define HID  192
#define HH   32
#define WW   32
#define MQ   (BB*LQ)       // 24576
#define MF   (BB*LIN)      // 32768
#define NOA  72            // 48 offs + 24 attn logits, fused

// ---------------- scratch (device globals; no allocs allowed) --------------
__device__ float g_qln [MQ*CC];
__device__ float g_fln [MF*CC];
__device__ float g_val [MF*CC];
__device__ float g_oa  [MQ*NOA];
__device__ float g_attn[MQ*CC];
__device__ float g_q2  [MQ*CC];
__device__ float g_x1  [MQ*HID];
__device__ float g_x2  [MQ*HID];
__device__ float g_w72 [CC*NOA];
__device__ float g_b72 [NOA];

// ---------------- mma + cp.async helpers -----------------------------------
__device__ __forceinline__ void mma_tf32(float* d, const uint32_t* a, const uint32_t* b) {
    asm volatile(
        "mma.sync.aligned.m16n8k8.row.col.f32.tf32.tf32.f32 "
        "{%0,%1,%2,%3}, {%4,%5,%6,%7}, {%8,%9}, {%0,%1,%2,%3};\n"
        : "+f"(d[0]), "+f"(d[1]), "+f"(d[2]), "+f"(d[3])
        : "r"(a[0]), "r"(a[1]), "r"(a[2]), "r"(a[3]), "r"(b[0]), "r"(b[1]));
}
__device__ __forceinline__ void cp16(uint32_t dst, const void* src, bool valid) {
    int sz = valid ? 16 : 0;
    asm volatile("cp.async.cg.shared.global [%0], [%1], 16, %2;\n"
                 :: "r"(dst), "l"(src), "r"(sz));
}
__device__ __forceinline__ void cp_commit() { asm volatile("cp.async.commit_group;\n"); }
template <int N> __device__ __forceinline__ void cp_wait() {
    asm volatile("cp.async.wait_group %0;\n" :: "n"(N));
}

// ---------------- tf32 tensor-core GEMM: C = A*W + bias (+R) ---------------
// BM=256, BN=128, BK=32, 256 threads, warps 4(m) x 2(n), warp tile 64x64.
// fp32 fed raw into tf32 MMA (HW truncates mantissa). 3-stage cp.async pipe.
#define ASTRIDE 36          // 32 + 4 pad  -> conflict-free A-fragment LDS
#define BSTRIDE 136         // 128 + 8 pad -> conflict-free B-fragment LDS
#define ASZ (256 * ASTRIDE) // 9216 u32
#define BSZ (32 * BSTRIDE)  // 4352 u32
#define SSZ (ASZ + BSZ)     // 13568 u32 per stage
#define NSTAGE 3
#define GEMM_SMEM (NSTAGE * SSZ * 4)   // 162,816 B

__global__ __launch_bounds__(256, 1)
void gemm_tf32_kernel(const float* __restrict__ A, const float* __restrict__ W,
                      const float* __restrict__ bias, const float* __restrict__ R,
                      float* __restrict__ C, int M, int N, int K) {
    extern __shared__ uint32_t sm[];

    const int t    = threadIdx.x;
    const int lane = t & 31;
    const int g    = lane >> 2;      // groupID 0..7
    const int tg   = lane & 3;       // thread-in-group 0..3
    const int wid  = t >> 5;
    const int wm   = wid & 3;        // m offset wm*64
    const int wn   = wid >> 2;       // n offset wn*64

    const int m0 = blockIdx.y * 256;
    const int n0 = blockIdx.x * 128;

    // staging coordinates (BM=256, BK=32)
    const int ra  = t >> 3;          // A rows ra + 32j, j=0..7
    const int ca  = (t & 7) * 4;     // A col offset within BK
    const int kb0 = t >> 5;          // B k-rows kb0 + 8j, j=0..3
    const int cb  = (t & 31) * 4;    // B col offset within BN
    const int nb  = n0 + cb;
    const bool bvalid = (nb < N);
    const int nbs = bvalid ? nb : 0;

    const uint32_t smem_u = (uint32_t)__cvta_generic_to_shared(sm);
    const float* Abase = A + (size_t)(m0 + ra) * K + ca;
    const float* Bbase = W + (size_t)kb0 * N + nbs;

    const int KT = K >> 5;           // chunks of 32 (K=768->24, K=192->6)

    auto issue = [&](int ck, int s) {
        const uint32_t sb = smem_u + (uint32_t)(s * SSZ * 4);
        const float* Ap = Abase + ck * 32;
        const float* Bp = Bbase + (size_t)ck * 32 * N;
        #pragma unroll
        for (int j = 0; j < 8; ++j)
            cp16(sb + ((ra + 32 * j) * ASTRIDE + ca) * 4,
                 Ap + (size_t)(32 * j) * K, true);
        #pragma unroll
        for (int j = 0; j < 4; ++j)
            cp16(sb + (ASZ + (kb0 + 8 * j) * BSTRIDE + cb) * 4,
                 Bp + (size_t)(8 * j) * N, bvalid);
    };

    // prologue: stages 0,1
    issue(0, 0); cp_commit();
    issue(1, 1); cp_commit();

    float acc[4][8][4] = {};

    for (int it = 0; it < KT; ++it) {
        cp_wait<1>();
        __syncthreads();

        const int nk = it + 2;
        if (nk < KT) { issue(nk, nk % NSTAGE); }
        cp_commit();

        const int cur = it % NSTAGE;
        const uint32_t* Ab = sm + cur * SSZ;
        const uint32_t* Bb = sm + cur * SSZ + ASZ;

        #pragma unroll
        for (int ks = 0; ks < 4; ++ks) {
            const int kb = ks * 8;
            uint32_t af[4][4], bf[8][2];
            #pragma unroll
            for (int mt = 0; mt < 4; ++mt) {
                const int r = wm * 64 + mt * 16 + g;
                af[mt][0] = Ab[r * ASTRIDE + kb + tg];
                af[mt][1] = Ab[(r + 8) * ASTRIDE + kb + tg];
                af[mt][2] = Ab[r * ASTRIDE + kb + tg + 4];
                af[mt][3] = Ab[(r + 8) * ASTRIDE + kb + tg + 4];
            }
            #pragma unroll
            for (int nt = 0; nt < 8; ++nt) {
                const int c = wn * 64 + nt * 8 + g;
                bf[nt][0] = Bb[(kb + tg) * BSTRIDE + c];
                bf[nt][1] = Bb[(kb + tg + 4) * BSTRIDE + c];
            }
            #pragma unroll
            for (int mt = 0; mt < 4; ++mt)
                #pragma unroll
                for (int nt = 0; nt < 8; ++nt)
                    mma_tf32(acc[mt][nt], af[mt], bf[nt]);
        }
        __syncthreads();   // all warps done with `cur` before it is overwritten
    }

    // epilogue: bias + optional residual
    #pragma unroll
    for (int mt = 0; mt < 4; ++mt) {
        const int gm = m0 + wm * 64 + mt * 16 + g;
        #pragma unroll
        for (int nt = 0; nt < 8; ++nt) {
            const int gn = n0 + wn * 64 + nt * 8 + 2 * tg;
            if (gn < N) {
                const float b0 = bias[gn], b1 = bias[gn + 1];
                float2 v0 = make_float2(acc[mt][nt][0] + b0, acc[mt][nt][1] + b1);
                float2 v1 = make_float2(acc[mt][nt][2] + b0, acc[mt][nt][3] + b1);
                const size_t i0 = (size_t)gm * N + gn;
                const size_t i1 = (size_t)(gm + 8) * N + gn;
                if (R) {
                    v0.x += R[i0];     v0.y += R[i0 + 1];
                    v1.x += R[i1];     v1.y += R[i1 + 1];
                }
                *(float2*)&C[i0] = v0;
                *(float2*)&C[i1] = v1;
            }
        }
    }
}

// ---------------- LayerNorm: one block per row, float4 ---------------------
__global__ void ln_kernel(const float* __restrict__ x, const float* __restrict__ w,
                          const float* __restrict__ b, float* __restrict__ y) {
    const int row = blockIdx.x;
    const int t = threadIdx.x;          // 192 threads, one float4 each
    const float4 v = ((const float4*)(x + (size_t)row * CC))[t];
    float s  = v.x + v.y + v.z + v.w;
    float ss = v.x*v.x + v.y*v.y + v.z*v.z + v.w*v.w;
    __shared__ float red0[6], red1[6];
    #pragma unroll
    for (int o = 16; o; o >>= 1) {
        s  += __shfl_down_sync(0xffffffffu, s,  o);
        ss += __shfl_down_sync(0xffffffffu, ss, o);
    }
    if ((t & 31) == 0) { red0[t >> 5] = s; red1[t >> 5] = ss; }
    __syncthreads();
    float st = 0.f, sst = 0.f;
    #pragma unroll
    for (int i = 0; i < 6; ++i) { st += red0[i]; sst += red1[i]; }
    const float mean = st * (1.f / CC);
    const float var  = sst * (1.f / CC) - mean * mean;
    const float inv  = rsqrtf(var + 1e-6f);
    const float4 wv = ((const float4*)w)[t];
    const float4 bv = ((const float4*)b)[t];
    float4 o;
    o.x = (v.x - mean) * inv * wv.x + bv.x;
    o.y = (v.y - mean) * inv * wv.y + bv.y;
    o.z = (v.z - mean) * inv * wv.z + bv.z;
    o.w = (v.w - mean) * inv * wv.w + bv.w;
    ((float4*)(y + (size_t)row * CC))[t] = o;
}

// ---------------- pack so_w|aw_w into one [768,72] weight ------------------
__global__ void pack_kernel(const float* __restrict__ so_w, const float* __restrict__ so_b,
                            const float* __restrict__ aw_w, const float* __restrict__ aw_b,
                            float* __restrict__ w72, float* __restrict__ b72) {
    int i = blockIdx.x * 256 + threadIdx.x;
    if (i < CC * NOA) {
        int k = i / NOA, n = i % NOA;
        w72[i] = (n < 48) ? so_w[k * 48 + n] : aw_w[k * 24 + (n - 48)];
    }
    if (i < NOA) b72[i] = (i < 48) ? so_b[i] : aw_b[i - 48];
}

// ------- softmax(attn weights) + bilinear sample + weighted reduce ---------
__global__ void sample_kernel(const float* __restrict__ refp, float* __restrict__ attn) {
    int q = blockIdx.x;           // b*LQ + lq
    int b = q / LQ;
    __shared__ float cw[NH][NP][4];
    __shared__ int   ci[NH][NP][4];
    __shared__ float lg[NH * NP];
    int t = threadIdx.x;
    if (t < NH * NP) lg[t] = g_oa[(size_t)q * NOA + 48 + t];
    __syncthreads();
    if (t < NH * NP) {
        int h = t >> 2;
        float l0 = lg[h*4+0], l1 = lg[h*4+1], l2 = lg[h*4+2], l3 = lg[h*4+3];
        float m  = fmaxf(fmaxf(l0, l1), fmaxf(l2, l3));
        float e0 = __expf(l0-m), e1 = __expf(l1-m), e2 = __expf(l2-m), e3 = __expf(l3-m);
        float aw = __expf(lg[t]-m) / (e0 + e1 + e2 + e3);
        float rx = refp[(size_t)q * 2 + 0];
        float ry = refp[(size_t)q * 2 + 1];
        float ox = g_oa[(size_t)q * NOA + t*2 + 0];
        float oy = g_oa[(size_t)q * NOA + t*2 + 1];
        float x = (rx + ox * (1.f / WL)) * WL - 0.5f;
        float y = (ry + oy * (1.f / HL)) * HL - 0.5f;
        float x0f = floorf(x), y0f = floorf(y);
        float wx = x - x0f, wy = y - y0f;
        int x0 = (int)x0f, y0 = (int)y0f;
        float ws[4] = {(1.f-wy)*(1.f-wx), (1.f-wy)*wx, wy*(1.f-wx), wy*wx};
        const int dys[4] = {0,0,1,1}, dxs[4] = {0,1,0,1};
        int h2 = t >> 2, p = t & 3;
        #pragma unroll
        for (int c2 = 0; c2 < 4; c2++) {
            int xi = x0 + dxs[c2], yi = y0 + dys[c2];
            bool valid = (xi >= 0) && (xi < WL) && (yi >= 0) && (yi < HL);
            ci[h2][p][c2] = valid ? (yi * WL + xi) : -1;
            cw[h2][p][c2] = valid ? ws[c2] * aw : 0.f;
        }
    }
    __syncthreads();
    const float* vb = g_val + (size_t)b * LIN * CC;
    const int h = t >> 5;                 // (t*4) >> 7
    float4 acc = make_float4(0.f, 0.f, 0.f, 0.f);
    #pragma unroll
    for (int p = 0; p < NP; p++)
        #pragma unroll
        for (int c2 = 0; c2 < 4; c2++) {
            int idx = ci[h][p][c2];
            if (idx >= 0) {
                float wgt = cw[h][p][c2];
                float4 v = ((const float4*)(vb + (size_t)idx * CC))[t];
                acc.x += v.x * wgt; acc.y += v.y * wgt;
                acc.z += v.z * wgt; acc.w += v.w * wgt;
            }
        }
    ((float4*)(attn + (size_t)q * CC))[t] = acc;
}

// ---------- depthwise 3x3 conv (SAME, zero pad) + bias + exact GELU --------
__global__ void dwconv_gelu_kernel(const float* __restrict__ x, const float* __restrict__ w,
                                   const float* __restrict__ bias, float* __restrict__ y) {
    int pg = blockIdx.x;                 // 0 .. B*LQ-1
    int c  = threadIdx.x;                // 0 .. 191
    int b    = pg / LQ;
    int rem  = pg % LQ;
    int chunk = rem / (HH * WW);
    int pix   = rem % (HH * WW);
    int py = pix >> 5, px = pix & 31;
    const float* xb = x + ((size_t)b * LQ + (size_t)chunk * HH * WW) * HID;
    float acc = bias[c];
    #pragma unroll
    for (int dy = -1; dy <= 1; dy++) {
        int yy = py + dy;
        if (yy < 0 || yy >= HH) continue;
        #pragma unroll
        for (int dx = -1; dx <= 1; dx++) {
            int xx = px + dx;
            if (xx < 0 || xx >= WW) continue;
            acc += xb[(size_t)(yy * WW + xx) * HID + c] * w[c * 9 + (dy + 1) * 3 + (dx + 1)];
        }
    }
    y[(size_t)pg * HID + c] = 0.5f * acc * (1.f + erff(acc * 0.70710678118654752f));
}

// ---------------------------------------------------------------------------
static inline void launch_gemm(const float* A, const float* W, const float* bias,
                               const float* R, float* C, int M, int N, int K) {
    dim3 grid((N + 127) / 128, M / 256);
    gemm_tf32_kernel<<<grid, 256, GEMM_SMEM>>>(A, W, bias, R, C, M, N, K);
}

extern "C" void kernel_launch(void* const* d_in, const int* in_sizes, int n_in,
                              void* d_out, int out_size) {
    const float* query = (const float*)d_in[0];
    const float* refp  = (const float*)d_in[1];
    const float* feat  = (const float*)d_in[2];
    const float* qn_w = (const float*)d_in[7];
    const float* qn_b = (const float*)d_in[8];
    const float* fn_w = (const float*)d_in[9];
    const float* fn_b = (const float*)d_in[10];
    const float* so_w = (const float*)d_in[11];
    const float* so_b = (const float*)d_in[12];
    const float* aw_w = (const float*)d_in[13];
    const float* aw_b = (const float*)d_in[14];
    const float* vp_w = (const float*)d_in[15];
    const float* vp_b = (const float*)d_in[16];
    const float* op_w = (const float*)d_in[17];
    const float* op_b = (const float*)d_in[18];
    const float* ffn_w = (const float*)d_in[19];
    const float* ffn_b = (const float*)d_in[20];
    const float* fc1_w = (const float*)d_in[21];
    const float* fc1_b = (const float*)d_in[22];
    const float* dw_w  = (const float*)d_in[23];
    const float* dw_b  = (const float*)d_in[24];
    const float* fc2_w = (const float*)d_in[25];
    const float* fc2_b = (const float*)d_in[26];
    float* out = (float*)d_out;

    float *p_qln, *p_fln, *p_val, *p_oa, *p_attn, *p_q2, *p_x1, *p_x2, *p_w72, *p_b72;
    cudaGetSymbolAddress((void**)&p_qln,  g_qln);
    cudaGetSymbolAddress((void**)&p_fln,  g_fln);
    cudaGetSymbolAddress((void**)&p_val,  g_val);
    cudaGetSymbolAddress((void**)&p_oa,   g_oa);
    cudaGetSymbolAddress((void**)&p_attn, g_attn);
    cudaGetSymbolAddress((void**)&p_q2,   g_q2);
    cudaGetSymbolAddress((void**)&p_x1,   g_x1);
    cudaGetSymbolAddress((void**)&p_x2,   g_x2);
    cudaGetSymbolAddress((void**)&p_w72,  g_w72);
    cudaGetSymbolAddress((void**)&p_b72,  g_b72);

    cudaFuncSetAttribute(gemm_tf32_kernel, cudaFuncAttributeMaxDynamicSharedMemorySize, GEMM_SMEM);

    // 1. LayerNorms + weight packing
    ln_kernel<<<MQ, 192>>>(query, qn_w, qn_b, p_qln);
    ln_kernel<<<MF, 192>>>(feat,  fn_w, fn_b, p_fln);
    pack_kernel<<<(CC*NOA + 255)/256, 256>>>(so_w, so_b, aw_w, aw_b, p_w72, p_b72);

    // 2. value = f_ln @ vp_w + vp_b        (32768 x 768 x 768)
    launch_gemm(p_fln, vp_w, vp_b, nullptr, p_val, MF, CC, CC);

    // 3. fused sampling-offset + attn-logit projection (24576 x 72 x 768)
    launch_gemm(p_qln, p_w72, p_b72, nullptr, p_oa, MQ, NOA, CC);

    // 4. softmax + bilinear sample + head-reduce
    sample_kernel<<<MQ, 192>>>(refp, p_attn);

    // 5. output projection + residual -> q2   (24576 x 768 x 768)
    launch_gemm(p_attn, op_w, op_b, query, p_q2, MQ, CC, CC);

    // 6. ConvFFN
    ln_kernel<<<MQ, 192>>>(p_q2, ffn_w, ffn_b, p_qln);
    launch_gemm(p_qln, fc1_w, fc1_b, nullptr, p_x1, MQ, HID, CC);
    dwconv_gelu_kernel<<<MQ, HID>>>(p_x1, dw_w, dw_b, p_x2);
    launch_gemm(p_x2, fc2_w, fc2_b, p_q2, out, MQ, CC, HID);
}

// round 7
// speedup vs baseline: 1.5911x; 1.5911x over previous
#include <cuda_runtime.h>
#include <cuda_fp16.h>
#include <math.h>
#include <stdint.h>

// ---------------- problem constants (fixed by setup_inputs) ----------------
#define BB   8
#define LQ   3072
#define CC   768
#define LIN  4096          // 64*64 feature tokens
#define HL   64
#define WL   64
#define NH   6
#define NP   4
#define HID  192
#define HH   32
#define WW   32
#define MQ   (BB*LQ)       // 24576
#define MF   (BB*LIN)      // 32768
#define NOA  72            // 48 offs + 24 attn logits, fused

// ---------------- scratch (device globals; no allocs allowed) --------------
__device__ __half g_qln16 [MQ*CC];
__device__ __half g_fln16 [MF*CC];
__device__ __half g_val16 [MF*CC];
__device__ __half g_attn16[MQ*CC];
__device__ __half g_x2h   [MQ*HID];
__device__ float  g_oa    [MQ*NOA];
__device__ float  g_q2    [MQ*CC];
__device__ float  g_x1    [MQ*HID];
// transposed fp16 weights [N][K]
__device__ __half g_vpT16 [CC*CC];
__device__ __half g_opT16 [CC*CC];
__device__ __half g_fc1T16[HID*CC];
__device__ __half g_fc2T16[CC*HID];
__device__ __half g_w72T16[NOA*CC];
__device__ float  g_b72   [NOA];

// ---------------- mma + cp.async helpers -----------------------------------
__device__ __forceinline__ void mma_fp16(float* d, const uint32_t* a, const uint32_t* b) {
    asm volatile(
        "mma.sync.aligned.m16n8k16.row.col.f32.f16.f16.f32 "
        "{%0,%1,%2,%3}, {%4,%5,%6,%7}, {%8,%9}, {%0,%1,%2,%3};\n"
        : "+f"(d[0]), "+f"(d[1]), "+f"(d[2]), "+f"(d[3])
        : "r"(a[0]), "r"(a[1]), "r"(a[2]), "r"(a[3]), "r"(b[0]), "r"(b[1]));
}
__device__ __forceinline__ void cp16(uint32_t dst, const void* src, bool valid) {
    int sz = valid ? 16 : 0;
    asm volatile("cp.async.cg.shared.global [%0], [%1], 16, %2;\n"
                 :: "r"(dst), "l"(src), "r"(sz));
}
__device__ __forceinline__ void cp_commit() { asm volatile("cp.async.commit_group;\n"); }
template <int N> __device__ __forceinline__ void cp_wait() {
    asm volatile("cp.async.wait_group %0;\n" :: "n"(N));
}

// ---------------- fp16 tensor-core GEMM: C = A*WT^T + bias (+R) ------------
// A [M,K] half row-major, WT [N,K] half row-major. BM=BN=128, BK=64 halves.
// 256 threads, warps 2(m) x 4(n), warp tile 64x32. 3-stage cp.async pipe,
// one __syncthreads per k-iteration.
#define ST 36                 // row stride in u32 (32 data + 4 pad) -> conflict-free
#define TSZ (128 * ST)        // one tile (A or B) in u32 = 4608
#define SSZ (2 * TSZ)         // stage = A + B = 9216 u32
#define NSTAGE 3
#define GEMM_SMEM (NSTAGE * SSZ * 4)   // 110,592 B

__global__ __launch_bounds__(256, 2)
void gemm_fp16_kernel(const __half* __restrict__ A, const __half* __restrict__ WT,
                      const float* __restrict__ bias, const float* __restrict__ R,
                      float* __restrict__ C, __half* __restrict__ Ch,
                      int M, int N, int K) {
    extern __shared__ uint32_t sm[];

    const int t    = threadIdx.x;
    const int lane = t & 31;
    const int g    = lane >> 2;      // groupID 0..7
    const int tg   = lane & 3;       // thread-in-group 0..3
    const int wid  = t >> 5;
    const int wm   = wid & 1;        // m offset wm*64
    const int wn   = wid >> 1;       // n offset wn*32

    const int m0 = blockIdx.y * 128;
    const int n0 = blockIdx.x * 128;

    // staging: 1024 16B-chunks per tile; thread t does rows (t>>3)+32j, halves col (t&7)*8
    const int sr = t >> 3;           // 0..31
    const int sc = (t & 7) * 8;      // half offset within 64-wide row
    const uint32_t smem_u = (uint32_t)__cvta_generic_to_shared(sm);
    const uint32_t soff = (uint32_t)((sr * ST + (t & 7) * 4) * 4);  // byte offset in tile

    const __half* Abase = A + (size_t)(m0 + sr) * K + sc;
    const __half* WTbase = WT + (size_t)sr * K + sc;   // row n0+sr handled via valid

    const int KT = K >> 6;           // chunks of 64 halves (768->12, 192->3)

    auto issue = [&](int ck, int s) {
        const uint32_t sb = smem_u + (uint32_t)(s * SSZ * 4);
        const __half* Ap = Abase + ck * 64;
        const __half* Bp = WTbase + ck * 64;
        #pragma unroll
        for (int j = 0; j < 4; ++j) {
            cp16(sb + soff + (uint32_t)(32 * j * ST * 4),
                 Ap + (size_t)(32 * j) * K, true);
            const int nr = n0 + sr + 32 * j;
            cp16(sb + (uint32_t)(TSZ * 4) + soff + (uint32_t)(32 * j * ST * 4),
                 Bp + (size_t)(n0 + 32 * j) * K, nr < N);
        }
    };

    // prologue: stages 0,1
    issue(0, 0); cp_commit();
    issue(1, 1); cp_commit();

    float acc[4][4][4] = {};

    for (int it = 0; it < KT; ++it) {
        cp_wait<1>();
        __syncthreads();

        const int nk = it + 2;
        if (nk < KT) issue(nk, nk % NSTAGE);
        cp_commit();

        const int cur = it % NSTAGE;
        const uint32_t* Ab = sm + cur * SSZ;
        const uint32_t* Bb = sm + cur * SSZ + TSZ;

        #pragma unroll
        for (int ks = 0; ks < 4; ++ks) {       // 4 x k16 per 64-half chunk
            const int kb = ks * 8;             // u32 offset within row
            uint32_t af[4][4], bf[4][2];
            #pragma unroll
            for (int mt = 0; mt < 4; ++mt) {
                const int r = wm * 64 + mt * 16 + g;
                af[mt][0] = Ab[r * ST + kb + tg];
                af[mt][1] = Ab[(r + 8) * ST + kb + tg];
                af[mt][2] = Ab[r * ST + kb + tg + 4];
                af[mt][3] = Ab[(r + 8) * ST + kb + tg + 4];
            }
            #pragma unroll
            for (int nt = 0; nt < 4; ++nt) {
                const int c = wn * 32 + nt * 8 + g;
                bf[nt][0] = Bb[c * ST + kb + tg];
                bf[nt][1] = Bb[c * ST + kb + tg + 4];
            }
            #pragma unroll
            for (int mt = 0; mt < 4; ++mt)
                #pragma unroll
                for (int nt = 0; nt < 4; ++nt)
                    mma_fp16(acc[mt][nt], af[mt], bf[nt]);
        }
    }

    // epilogue: bias + optional residual; write float C and/or half Ch
    #pragma unroll
    for (int mt = 0; mt < 4; ++mt) {
        const int gm = m0 + wm * 64 + mt * 16 + g;
        #pragma unroll
        for (int nt = 0; nt < 4; ++nt) {
            const int gn = n0 + wn * 32 + nt * 8 + 2 * tg;
            if (gn < N) {
                const float b0 = bias[gn], b1 = bias[gn + 1];
                float2 v0 = make_float2(acc[mt][nt][0] + b0, acc[mt][nt][1] + b1);
                float2 v1 = make_float2(acc[mt][nt][2] + b0, acc[mt][nt][3] + b1);
                const size_t i0 = (size_t)gm * N + gn;
                const size_t i1 = (size_t)(gm + 8) * N + gn;
                if (R) {
                    v0.x += R[i0];     v0.y += R[i0 + 1];
                    v1.x += R[i1];     v1.y += R[i1 + 1];
                }
                if (C) {
                    *(float2*)&C[i0] = v0;
                    *(float2*)&C[i1] = v1;
                }
                if (Ch) {
                    *(__half2*)&Ch[i0] = __floats2half2_rn(v0.x, v0.y);
                    *(__half2*)&Ch[i1] = __floats2half2_rn(v1.x, v1.y);
                }
            }
        }
    }
}

// ---------------- LayerNorm: one block per row, float4 in, half out --------
__global__ void ln_kernel(const float* __restrict__ x, const float* __restrict__ w,
                          const float* __restrict__ b, __half* __restrict__ y) {
    const int row = blockIdx.x;
    const int t = threadIdx.x;          // 192 threads, one float4 each
    const float4 v = ((const float4*)(x + (size_t)row * CC))[t];
    float s  = v.x + v.y + v.z + v.w;
    float ss = v.x*v.x + v.y*v.y + v.z*v.z + v.w*v.w;
    __shared__ float red0[6], red1[6];
    #pragma unroll
    for (int o = 16; o; o >>= 1) {
        s  += __shfl_down_sync(0xffffffffu, s,  o);
        ss += __shfl_down_sync(0xffffffffu, ss, o);
    }
    if ((t & 31) == 0) { red0[t >> 5] = s; red1[t >> 5] = ss; }
    __syncthreads();
    float st = 0.f, sst = 0.f;
    #pragma unroll
    for (int i = 0; i < 6; ++i) { st += red0[i]; sst += red1[i]; }
    const float mean = st * (1.f / CC);
    const float var  = sst * (1.f / CC) - mean * mean;
    const float inv  = rsqrtf(var + 1e-6f);
    const float4 wv = ((const float4*)w)[t];
    const float4 bv = ((const float4*)b)[t];
    __half2 h0 = __floats2half2_rn((v.x - mean) * inv * wv.x + bv.x,
                                   (v.y - mean) * inv * wv.y + bv.y);
    __half2 h1 = __floats2half2_rn((v.z - mean) * inv * wv.z + bv.z,
                                   (v.w - mean) * inv * wv.w + bv.w);
    uint2 o2 = make_uint2(*(uint32_t*)&h0, *(uint32_t*)&h1);
    *(uint2*)&y[(size_t)row * CC + t * 4] = o2;
}

// ---------------- transpose + fp16 convert: src[K][N] -> dst[N][K] ---------
__global__ void transpose_h_kernel(const float* __restrict__ src, __half* __restrict__ dst,
                                   int K, int N) {
    __shared__ float tile[32][33];
    const int kb = blockIdx.y * 32, nb = blockIdx.x * 32;
    const int tx = threadIdx.x, ty = threadIdx.y;   // 32 x 8
    #pragma unroll
    for (int i = 0; i < 32; i += 8) {
        const int k = kb + ty + i, n = nb + tx;
        tile[ty + i][tx] = (k < K && n < N) ? src[(size_t)k * N + n] : 0.f;
    }
    __syncthreads();
    #pragma unroll
    for (int i = 0; i < 32; i += 8) {
        const int n = nb + ty + i, k = kb + tx;
        if (n < N && k < K) dst[(size_t)n * K + k] = __float2half_rn(tile[tx][ty + i]);
    }
}

// ---------------- pack so_w|aw_w transposed into half [72][768] ------------
__global__ void pack72_kernel(const float* __restrict__ so_w, const float* __restrict__ so_b,
                              const float* __restrict__ aw_w, const float* __restrict__ aw_b,
                              __half* __restrict__ w72T, float* __restrict__ b72) {
    int i = blockIdx.x * 256 + threadIdx.x;
    if (i < NOA * CC) {
        int n = i / CC, k = i % CC;
        float v = (n < 48) ? so_w[k * 48 + n] : aw_w[k * 24 + (n - 48)];
        w72T[i] = __float2half_rn(v);
    }
    if (i < NOA) b72[i] = (i < 48) ? so_b[i] : aw_b[i - 48];
}

// ------- softmax(attn weights) + bilinear sample + weighted reduce ---------
// One block per query; 192 threads, 4 halves per thread.
__global__ void sample_kernel(const float* __restrict__ refp, __half* __restrict__ attn) {
    int q = blockIdx.x;           // b*LQ + lq
    int b = q / LQ;
    __shared__ float cw[NH][NP][4];
    __shared__ int   ci[NH][NP][4];
    __shared__ float lg[NH * NP];
    int t = threadIdx.x;
    if (t < NH * NP) lg[t] = g_oa[(size_t)q * NOA + 48 + t];
    __syncthreads();
    if (t < NH * NP) {
        int h = t >> 2;
        float l0 = lg[h*4+0], l1 = lg[h*4+1], l2 = lg[h*4+2], l3 = lg[h*4+3];
        float m  = fmaxf(fmaxf(l0, l1), fmaxf(l2, l3));
        float e0 = __expf(l0-m), e1 = __expf(l1-m), e2 = __expf(l2-m), e3 = __expf(l3-m);
        float aw = __expf(lg[t]-m) / (e0 + e1 + e2 + e3);
        float rx = refp[(size_t)q * 2 + 0];
        float ry = refp[(size_t)q * 2 + 1];
        float ox = g_oa[(size_t)q * NOA + t*2 + 0];
        float oy = g_oa[(size_t)q * NOA + t*2 + 1];
        float x = (rx + ox * (1.f / WL)) * WL - 0.5f;
        float y = (ry + oy * (1.f / HL)) * HL - 0.5f;
        float x0f = floorf(x), y0f = floorf(y);
        float wx = x - x0f, wy = y - y0f;
        int x0 = (int)x0f, y0 = (int)y0f;
        float ws[4] = {(1.f-wy)*(1.f-wx), (1.f-wy)*wx, wy*(1.f-wx), wy*wx};
        const int dys[4] = {0,0,1,1}, dxs[4] = {0,1,0,1};
        int h2 = t >> 2, p = t & 3;
        #pragma unroll
        for (int c2 = 0; c2 < 4; c2++) {
            int xi = x0 + dxs[c2], yi = y0 + dys[c2];
            bool valid = (xi >= 0) && (xi < WL) && (yi >= 0) && (yi < HL);
            ci[h2][p][c2] = valid ? (yi * WL + xi) : -1;
            cw[h2][p][c2] = valid ? ws[c2] * aw : 0.f;
        }
    }
    __syncthreads();
    const __half* vb = g_val16 + (size_t)b * LIN * CC;
    const int h = t >> 5;                 // (t*4) >> 7
    float4 acc = make_float4(0.f, 0.f, 0.f, 0.f);
    #pragma unroll
    for (int p = 0; p < NP; p++)
        #pragma unroll
        for (int c2 = 0; c2 < 4; c2++) {
            int idx = ci[h][p][c2];
            if (idx >= 0) {
                float wgt = cw[h][p][c2];
                uint2 raw = *(const uint2*)&vb[(size_t)idx * CC + t * 4];
                float2 f0 = __half22float2(*(__half2*)&raw.x);
                float2 f1 = __half22float2(*(__half2*)&raw.y);
                acc.x += f0.x * wgt; acc.y += f0.y * wgt;
                acc.z += f1.x * wgt; acc.w += f1.y * wgt;
            }
        }
    __half2 h0 = __floats2half2_rn(acc.x, acc.y);
    __half2 h1 = __floats2half2_rn(acc.z, acc.w);
    uint2 o2 = make_uint2(*(uint32_t*)&h0, *(uint32_t*)&h1);
    *(uint2*)&attn[(size_t)q * CC + t * 4] = o2;
}

// ---------- depthwise 3x3 conv (SAME, zero pad) + bias + exact GELU --------
__global__ void dwconv_gelu_kernel(const float* __restrict__ x, const float* __restrict__ w,
                                   const float* __restrict__ bias, __half* __restrict__ y) {
    int pg = blockIdx.x;                 // 0 .. B*LQ-1
    int c  = threadIdx.x;                // 0 .. 191
    int b    = pg / LQ;
    int rem  = pg % LQ;
    int chunk = rem / (HH * WW);
    int pix   = rem % (HH * WW);
    int py = pix >> 5, px = pix & 31;
    const float* xb = x + ((size_t)b * LQ + (size_t)chunk * HH * WW) * HID;
    float acc = bias[c];
    #pragma unroll
    for (int dy = -1; dy <= 1; dy++) {
        int yy = py + dy;
        if (yy < 0 || yy >= HH) continue;
        #pragma unroll
        for (int dx = -1; dx <= 1; dx++) {
            int xx = px + dx;
            if (xx < 0 || xx >= WW) continue;
            acc += xb[(size_t)(yy * WW + xx) * HID + c] * w[c * 9 + (dy + 1) * 3 + (dx + 1)];
        }
    }
    float gl = 0.5f * acc * (1.f + erff(acc * 0.70710678118654752f));
    y[(size_t)pg * HID + c] = __float2half_rn(gl);
}

// ---------------------------------------------------------------------------
static inline void launch_gemm(const __half* A, const __half* WT, const float* bias,
                               const float* R, float* C, __half* Ch, int M, int N, int K) {
    dim3 grid((N + 127) / 128, M / 128);
    gemm_fp16_kernel<<<grid, 256, GEMM_SMEM>>>(A, WT, bias, R, C, Ch, M, N, K);
}

extern "C" void kernel_launch(void* const* d_in, const int* in_sizes, int n_in,
                              void* d_out, int out_size) {
    const float* query = (const float*)d_in[0];
    const float* refp  = (const float*)d_in[1];
    const float* feat  = (const float*)d_in[2];
    const float* qn_w = (const float*)d_in[7];
    const float* qn_b = (const float*)d_in[8];
    const float* fn_w = (const float*)d_in[9];
    const float* fn_b = (const float*)d_in[10];
    const float* so_w = (const float*)d_in[11];
    const float* so_b = (const float*)d_in[12];
    const float* aw_w = (const float*)d_in[13];
    const float* aw_b = (const float*)d_in[14];
    const float* vp_w = (const float*)d_in[15];
    const float* vp_b = (const float*)d_in[16];
    const float* op_w = (const float*)d_in[17];
    const float* op_b = (const float*)d_in[18];
    const float* ffn_w = (const float*)d_in[19];
    const float* ffn_b = (const float*)d_in[20];
    const float* fc1_w = (const float*)d_in[21];
    const float* fc1_b = (const float*)d_in[22];
    const float* dw_w  = (const float*)d_in[23];
    const float* dw_b  = (const float*)d_in[24];
    const float* fc2_w = (const float*)d_in[25];
    const float* fc2_b = (const float*)d_in[26];
    float* out = (float*)d_out;

    __half *p_qln16, *p_fln16, *p_val16, *p_attn16, *p_x2h;
    __half *p_vpT, *p_opT, *p_fc1T, *p_fc2T, *p_w72T;
    float *p_oa, *p_q2, *p_x1, *p_b72;
    cudaGetSymbolAddress((void**)&p_qln16,  g_qln16);
    cudaGetSymbolAddress((void**)&p_fln16,  g_fln16);
    cudaGetSymbolAddress((void**)&p_val16,  g_val16);
    cudaGetSymbolAddress((void**)&p_attn16, g_attn16);
    cudaGetSymbolAddress((void**)&p_x2h,    g_x2h);
    cudaGetSymbolAddress((void**)&p_vpT,    g_vpT16);
    cudaGetSymbolAddress((void**)&p_opT,    g_opT16);
    cudaGetSymbolAddress((void**)&p_fc1T,   g_fc1T16);
    cudaGetSymbolAddress((void**)&p_fc2T,   g_fc2T16);
    cudaGetSymbolAddress((void**)&p_w72T,   g_w72T16);
    cudaGetSymbolAddress((void**)&p_oa,     g_oa);
    cudaGetSymbolAddress((void**)&p_q2,     g_q2);
    cudaGetSymbolAddress((void**)&p_x1,     g_x1);
    cudaGetSymbolAddress((void**)&p_b72,    g_b72);

    cudaFuncSetAttribute(gemm_fp16_kernel, cudaFuncAttributeMaxDynamicSharedMemorySize, GEMM_SMEM);

    // 0. weight prep: transpose to [N][K] + fp16 convert
    transpose_h_kernel<<<dim3(24, 24), dim3(32, 8)>>>(vp_w,  p_vpT,  CC, CC);
    transpose_h_kernel<<<dim3(24, 24), dim3(32, 8)>>>(op_w,  p_opT,  CC, CC);
    transpose_h_kernel<<<dim3(6, 24),  dim3(32, 8)>>>(fc1_w, p_fc1T, CC, HID);
    transpose_h_kernel<<<dim3(24, 6),  dim3(32, 8)>>>(fc2_w, p_fc2T, HID, CC);
    pack72_kernel<<<(NOA*CC + 255)/256, 256>>>(so_w, so_b, aw_w, aw_b, p_w72T, p_b72);

    // 1. LayerNorms (fp32 in -> fp16 out)
    ln_kernel<<<MQ, 192>>>(query, qn_w, qn_b, p_qln16);
    ln_kernel<<<MF, 192>>>(feat,  fn_w, fn_b, p_fln16);

    // 2. value = f_ln @ vp_w + vp_b   (32768 x 768 x 768), half output
    launch_gemm(p_fln16, p_vpT, vp_b, nullptr, nullptr, p_val16, MF, CC, CC);

    // 3. fused sampling-offset + attn-logit projection (24576 x 72 x 768)
    launch_gemm(p_qln16, p_w72T, p_b72, nullptr, p_oa, nullptr, MQ, NOA, CC);

    // 4. softmax + bilinear sample + head-reduce (half in/out)
    sample_kernel<<<MQ, 192>>>(refp, p_attn16);

    // 5. output projection + residual -> q2 fp32   (24576 x 768 x 768)
    launch_gemm(p_attn16, p_opT, op_b, query, p_q2, nullptr, MQ, CC, CC);

    // 6. ConvFFN
    ln_kernel<<<MQ, 192>>>(p_q2, ffn_w, ffn_b, p_qln16);
    launch_gemm(p_qln16, p_fc1T, fc1_b, nullptr, p_x1, nullptr, MQ, HID, CC);
    dwconv_gelu_kernel<<<MQ, HID>>>(p_x1, dw_w, dw_b, p_x2h);
    launch_gemm(p_x2h, p_fc2T, fc2_b, p_q2, out, nullptr, MQ, CC, HID);
}

// round 8
// speedup vs baseline: 1.6702x; 1.0497x over previous
#include <cuda_runtime.h>
#include <cuda_fp16.h>
#include <math.h>
#include <stdint.h>

// ---------------- problem constants (fixed by setup_inputs) ----------------
#define BB   8
#define LQ   3072
#define CC   768
#define LIN  4096          // 64*64 feature tokens
#define HL   64
#define WL   64
#define NH   6
#define NP   4
#define HID  192
#define HH   32
#define WW   32
#define MQ   (BB*LQ)       // 24576
#define MF   (BB*LIN)      // 32768
#define NOA  72            // 48 offs + 24 attn logits, fused

// ---------------- scratch (device globals; no allocs allowed) --------------
__device__ __half g_qln16 [MQ*CC];
__device__ __half g_fln16 [MF*CC];
__device__ __half g_val16 [MF*CC];
__device__ __half g_attn16[MQ*CC];
__device__ __half g_x1h   [MQ*HID];
__device__ __half g_x2h   [MQ*HID];
__device__ float  g_oa    [MQ*NOA];
__device__ float  g_q2    [MQ*CC];
// transposed fp16 weights [N][K]
__device__ __half g_vpT16 [CC*CC];
__device__ __half g_opT16 [CC*CC];
__device__ __half g_fc1T16[HID*CC];
__device__ __half g_fc2T16[CC*HID];
__device__ __half g_w72T16[NOA*CC];
__device__ float  g_b72   [NOA];

// ---------------- mma / ldmatrix / cp.async helpers -------------------------
__device__ __forceinline__ void mma_fp16(float* d, const uint32_t* a, const uint32_t* b) {
    asm volatile(
        "mma.sync.aligned.m16n8k16.row.col.f32.f16.f16.f32 "
        "{%0,%1,%2,%3}, {%4,%5,%6,%7}, {%8,%9}, {%0,%1,%2,%3};\n"
        : "+f"(d[0]), "+f"(d[1]), "+f"(d[2]), "+f"(d[3])
        : "r"(a[0]), "r"(a[1]), "r"(a[2]), "r"(a[3]), "r"(b[0]), "r"(b[1]));
}
__device__ __forceinline__ void ldsm_x4(uint32_t* r, uint32_t addr) {
    asm volatile("ldmatrix.sync.aligned.m8n8.x4.shared.b16 {%0,%1,%2,%3}, [%4];"
                 : "=r"(r[0]), "=r"(r[1]), "=r"(r[2]), "=r"(r[3]) : "r"(addr));
}
__device__ __forceinline__ void cp16(uint32_t dst, const void* src, bool valid) {
    int sz = valid ? 16 : 0;
    asm volatile("cp.async.cg.shared.global [%0], [%1], 16, %2;\n"
                 :: "r"(dst), "l"(src), "r"(sz));
}
__device__ __forceinline__ void cp_commit() { asm volatile("cp.async.commit_group;\n"); }
template <int N> __device__ __forceinline__ void cp_wait() {
    asm volatile("cp.async.wait_group %0;\n" :: "n"(N));
}

// ---------------- fp16 tensor-core GEMM: C = A*WT^T + bias (+R) ------------
// A [M,K] half row-major, WT [N,K] half row-major. BM=BN=128, BK=64 halves.
// 256 threads, warps 2(m) x 4(n), warp tile 64x32. 3-stage cp.async pipe.
// Fragment fetch via ldmatrix.x4 (6 per k16-step instead of 24 scalar LDS).
#define ST 36                 // row stride in u32 (32 data + 4 pad) -> conflict-free
#define STB (ST*4)            // 144 bytes
#define TSZ (128 * ST)        // one tile (A or B) in u32 = 4608
#define SSZ (2 * TSZ)         // stage = A + B = 9216 u32
#define NSTAGE 3
#define GEMM_SMEM (NSTAGE * SSZ * 4)   // 110,592 B

__global__ __launch_bounds__(256, 2)
void gemm_fp16_kernel(const __half* __restrict__ A, const __half* __restrict__ WT,
                      const float* __restrict__ bias, const float* __restrict__ R,
                      float* __restrict__ C, __half* __restrict__ Ch,
                      int M, int N, int K) {
    extern __shared__ uint32_t sm[];

    const int t    = threadIdx.x;
    const int lane = t & 31;
    const int g    = lane >> 2;      // groupID 0..7
    const int tg   = lane & 3;       // thread-in-group 0..3
    const int wid  = t >> 5;
    const int wm   = wid & 1;        // m offset wm*64
    const int wn   = wid >> 1;       // n offset wn*32

    const int m0 = blockIdx.y * 128;
    const int n0 = blockIdx.x * 128;

    // staging: thread t loads rows (t>>3)+32j, 16B chunk (t&7)
    const int sr = t >> 3;           // 0..31
    const int sc = (t & 7) * 8;      // half offset within 64-wide row
    const uint32_t smem_u = (uint32_t)__cvta_generic_to_shared(sm);
    const uint32_t soff = (uint32_t)(sr * STB + (t & 7) * 16);

    const __half* Abase = A + (size_t)(m0 + sr) * K + sc;
    const __half* WTbase = WT + (size_t)sr * K + sc;

    const int KT = K >> 6;           // chunks of 64 halves (768->12, 192->3)

    auto issue = [&](int ck, int s) {
        const uint32_t sb = smem_u + (uint32_t)(s * SSZ * 4);
        const __half* Ap = Abase + ck * 64;
        const __half* Bp = WTbase + ck * 64;
        #pragma unroll
        for (int j = 0; j < 4; ++j) {
            cp16(sb + soff + (uint32_t)(32 * j * STB),
                 Ap + (size_t)(32 * j) * K, true);
            const int nr = n0 + sr + 32 * j;
            cp16(sb + (uint32_t)(TSZ * 4) + soff + (uint32_t)(32 * j * STB),
                 Bp + (size_t)(n0 + 32 * j) * K, nr < N);
        }
    };

    // ldmatrix per-lane row offsets (stage/ks independent)
    // A matrices M0..M3 = {rows+0 klo, rows+8 klo, rows+0 khi, rows+8 khi}
    const int rowA  = (lane & 7) + ((lane >> 3) & 1) * 8;
    const uint32_t kselA = (uint32_t)(lane >> 4) * 16;
    uint32_t aoff[4];
    #pragma unroll
    for (int mt = 0; mt < 4; ++mt)
        aoff[mt] = (uint32_t)((wm * 64 + mt * 16 + rowA) * STB) + kselA;
    // B matrices M0..M3 = {n+0 klo, n+0 khi, n+8 klo, n+8 khi}  (per pair p)
    const int rowB  = (lane & 7) + ((lane >> 4) & 1) * 8;
    const uint32_t kselB = (uint32_t)((lane >> 3) & 1) * 16;
    uint32_t boff[2];
    #pragma unroll
    for (int p = 0; p < 2; ++p)
        boff[p] = (uint32_t)((wn * 32 + p * 16 + rowB) * STB) + kselB;

    // prologue: stages 0,1
    issue(0, 0); cp_commit();
    issue(1, 1); cp_commit();

    float acc[4][4][4] = {};

    for (int it = 0; it < KT; ++it) {
        cp_wait<1>();
        __syncthreads();

        const int nk = it + 2;
        if (nk < KT) issue(nk, nk % NSTAGE);
        cp_commit();

        const int cur = it % NSTAGE;
        const uint32_t abase = smem_u + (uint32_t)(cur * SSZ * 4);
        const uint32_t bbase = abase + (uint32_t)(TSZ * 4);

        #pragma unroll
        for (int ks = 0; ks < 4; ++ks) {       // 4 x k16 per 64-half chunk
            const uint32_t kbyte = (uint32_t)(ks * 32);
            uint32_t af[4][4], bf[2][4];
            #pragma unroll
            for (int mt = 0; mt < 4; ++mt)
                ldsm_x4(af[mt], abase + aoff[mt] + kbyte);
            #pragma unroll
            for (int p = 0; p < 2; ++p)
                ldsm_x4(bf[p], bbase + boff[p] + kbyte);
            #pragma unroll
            for (int mt = 0; mt < 4; ++mt) {
                mma_fp16(acc[mt][0], af[mt], &bf[0][0]);
                mma_fp16(acc[mt][1], af[mt], &bf[0][2]);
                mma_fp16(acc[mt][2], af[mt], &bf[1][0]);
                mma_fp16(acc[mt][3], af[mt], &bf[1][2]);
            }
        }
    }

    // epilogue: bias + optional residual; write float C and/or half Ch
    #pragma unroll
    for (int mt = 0; mt < 4; ++mt) {
        const int gm = m0 + wm * 64 + mt * 16 + g;
        #pragma unroll
        for (int nt = 0; nt < 4; ++nt) {
            const int gn = n0 + wn * 32 + nt * 8 + 2 * tg;
            if (gn < N) {
                const float b0 = bias[gn], b1 = bias[gn + 1];
                float2 v0 = make_float2(acc[mt][nt][0] + b0, acc[mt][nt][1] + b1);
                float2 v1 = make_float2(acc[mt][nt][2] + b0, acc[mt][nt][3] + b1);
                const size_t i0 = (size_t)gm * N + gn;
                const size_t i1 = (size_t)(gm + 8) * N + gn;
                if (R) {
                    v0.x += R[i0];     v0.y += R[i0 + 1];
                    v1.x += R[i1];     v1.y += R[i1 + 1];
                }
                if (C) {
                    *(float2*)&C[i0] = v0;
                    *(float2*)&C[i1] = v1;
                }
                if (Ch) {
                    *(__half2*)&Ch[i0] = __floats2half2_rn(v0.x, v0.y);
                    *(__half2*)&Ch[i1] = __floats2half2_rn(v1.x, v1.y);
                }
            }
        }
    }
}

// ---------------- LayerNorm: one block per row, float4 in, half out --------
__global__ void ln_kernel(const float* __restrict__ x, const float* __restrict__ w,
                          const float* __restrict__ b, __half* __restrict__ y) {
    const int row = blockIdx.x;
    const int t = threadIdx.x;          // 192 threads, one float4 each
    const float4 v = ((const float4*)(x + (size_t)row * CC))[t];
    float s  = v.x + v.y + v.z + v.w;
    float ss = v.x*v.x + v.y*v.y + v.z*v.z + v.w*v.w;
    __shared__ float red0[6], red1[6];
    #pragma unroll
    for (int o = 16; o; o >>= 1) {
        s  += __shfl_down_sync(0xffffffffu, s,  o);
        ss += __shfl_down_sync(0xffffffffu, ss, o);
    }
    if ((t & 31) == 0) { red0[t >> 5] = s; red1[t >> 5] = ss; }
    __syncthreads();
    float st = 0.f, sst = 0.f;
    #pragma unroll
    for (int i = 0; i < 6; ++i) { st += red0[i]; sst += red1[i]; }
    const float mean = st * (1.f / CC);
    const float var  = sst * (1.f / CC) - mean * mean;
    const float inv  = rsqrtf(var + 1e-6f);
    const float4 wv = ((const float4*)w)[t];
    const float4 bv = ((const float4*)b)[t];
    __half2 h0 = __floats2half2_rn((v.x - mean) * inv * wv.x + bv.x,
                                   (v.y - mean) * inv * wv.y + bv.y);
    __half2 h1 = __floats2half2_rn((v.z - mean) * inv * wv.z + bv.z,
                                   (v.w - mean) * inv * wv.w + bv.w);
    uint2 o2 = make_uint2(*(uint32_t*)&h0, *(uint32_t*)&h1);
    *(uint2*)&y[(size_t)row * CC + t * 4] = o2;
}

// ---------------- transpose + fp16 convert: src[K][N] -> dst[N][K] ---------
__global__ void transpose_h_kernel(const float* __restrict__ src, __half* __restrict__ dst,
                                   int K, int N) {
    __shared__ float tile[32][33];
    const int kb = blockIdx.y * 32, nb = blockIdx.x * 32;
    const int tx = threadIdx.x, ty = threadIdx.y;   // 32 x 8
    #pragma unroll
    for (int i = 0; i < 32; i += 8) {
        const int k = kb + ty + i, n = nb + tx;
        tile[ty + i][tx] = (k < K && n < N) ? src[(size_t)k * N + n] : 0.f;
    }
    __syncthreads();
    #pragma unroll
    for (int i = 0; i < 32; i += 8) {
        const int n = nb + ty + i, k = kb + tx;
        if (n < N && k < K) dst[(size_t)n * K + k] = __float2half_rn(tile[tx][ty + i]);
    }
}

// ---------------- pack so_w|aw_w transposed into half [72][768] ------------
__global__ void pack72_kernel(const float* __restrict__ so_w, const float* __restrict__ so_b,
                              const float* __restrict__ aw_w, const float* __restrict__ aw_b,
                              __half* __restrict__ w72T, float* __restrict__ b72) {
    int i = blockIdx.x * 256 + threadIdx.x;
    if (i < NOA * CC) {
        int n = i / CC, k = i % CC;
        float v = (n < 48) ? so_w[k * 48 + n] : aw_w[k * 24 + (n - 48)];
        w72T[i] = __float2half_rn(v);
    }
    if (i < NOA) b72[i] = (i < 48) ? so_b[i] : aw_b[i - 48];
}

// ------- softmax(attn weights) + bilinear sample + weighted reduce ---------
// One block per query; 192 threads, 4 halves per thread.
__global__ void sample_kernel(const float* __restrict__ refp, __half* __restrict__ attn) {
    int q = blockIdx.x;           // b*LQ + lq
    int b = q / LQ;
    __shared__ float cw[NH][NP][4];
    __shared__ int   ci[NH][NP][4];
    __shared__ float lg[NH * NP];
    int t = threadIdx.x;
    if (t < NH * NP) lg[t] = g_oa[(size_t)q * NOA + 48 + t];
    __syncthreads();
    if (t < NH * NP) {
        int h = t >> 2;
        float l0 = lg[h*4+0], l1 = lg[h*4+1], l2 = lg[h*4+2], l3 = lg[h*4+3];
        float m  = fmaxf(fmaxf(l0, l1), fmaxf(l2, l3));
        float e0 = __expf(l0-m), e1 = __expf(l1-m), e2 = __expf(l2-m), e3 = __expf(l3-m);
        float aw = __expf(lg[t]-m) / (e0 + e1 + e2 + e3);
        float rx = refp[(size_t)q * 2 + 0];
        float ry = refp[(size_t)q * 2 + 1];
        float ox = g_oa[(size_t)q * NOA + t*2 + 0];
        float oy = g_oa[(size_t)q * NOA + t*2 + 1];
        float x = (rx + ox * (1.f / WL)) * WL - 0.5f;
        float y = (ry + oy * (1.f / HL)) * HL - 0.5f;
        float x0f = floorf(x), y0f = floorf(y);
        float wx = x - x0f, wy = y - y0f;
        int x0 = (int)x0f, y0 = (int)y0f;
        float ws[4] = {(1.f-wy)*(1.f-wx), (1.f-wy)*wx, wy*(1.f-wx), wy*wx};
        const int dys[4] = {0,0,1,1}, dxs[4] = {0,1,0,1};
        int h2 = t >> 2, p = t & 3;
        #pragma unroll
        for (int c2 = 0; c2 < 4; c2++) {
            int xi = x0 + dxs[c2], yi = y0 + dys[c2];
            bool valid = (xi >= 0) && (xi < WL) && (yi >= 0) && (yi < HL);
            ci[h2][p][c2] = valid ? (yi * WL + xi) : -1;
            cw[h2][p][c2] = valid ? ws[c2] * aw : 0.f;
        }
    }
    __syncthreads();
    const __half* vb = g_val16 + (size_t)b * LIN * CC;
    const int h = t >> 5;                 // (t*4) >> 7
    float4 acc = make_float4(0.f, 0.f, 0.f, 0.f);
    #pragma unroll
    for (int p = 0; p < NP; p++)
        #pragma unroll
        for (int c2 = 0; c2 < 4; c2++) {
            int idx = ci[h][p][c2];
            if (idx >= 0) {
                float wgt = cw[h][p][c2];
                uint2 raw = *(const uint2*)&vb[(size_t)idx * CC + t * 4];
                float2 f0 = __half22float2(*(__half2*)&raw.x);
                float2 f1 = __half22float2(*(__half2*)&raw.y);
                acc.x += f0.x * wgt; acc.y += f0.y * wgt;
                acc.z += f1.x * wgt; acc.w += f1.y * wgt;
            }
        }
    __half2 h0 = __floats2half2_rn(acc.x, acc.y);
    __half2 h1 = __floats2half2_rn(acc.z, acc.w);
    uint2 o2 = make_uint2(*(uint32_t*)&h0, *(uint32_t*)&h1);
    *(uint2*)&attn[(size_t)q * CC + t * 4] = o2;
}

// ---------- depthwise 3x3 conv (SAME, zero pad) + bias + exact GELU --------
// half in, half out, fp32 accumulate.
__global__ void dwconv_gelu_kernel(const __half* __restrict__ x, const float* __restrict__ w,
                                   const float* __restrict__ bias, __half* __restrict__ y) {
    int pg = blockIdx.x;                 // 0 .. B*LQ-1
    int c  = threadIdx.x;                // 0 .. 191
    int b    = pg / LQ;
    int rem  = pg % LQ;
    int chunk = rem / (HH * WW);
    int pix   = rem % (HH * WW);
    int py = pix >> 5, px = pix & 31;
    const __half* xb = x + ((size_t)b * LQ + (size_t)chunk * HH * WW) * HID;
    float acc = bias[c];
    #pragma unroll
    for (int dy = -1; dy <= 1; dy++) {
        int yy = py + dy;
        if (yy < 0 || yy >= HH) continue;
        #pragma unroll
        for (int dx = -1; dx <= 1; dx++) {
            int xx = px + dx;
            if (xx < 0 || xx >= WW) continue;
            acc += __half2float(xb[(size_t)(yy * WW + xx) * HID + c])
                   * w[c * 9 + (dy + 1) * 3 + (dx + 1)];
        }
    }
    float gl = 0.5f * acc * (1.f + erff(acc * 0.70710678118654752f));
    y[(size_t)pg * HID + c] = __float2half_rn(gl);
}

// ---------------------------------------------------------------------------
static inline void launch_gemm(const __half* A, const __half* WT, const float* bias,
                               const float* R, float* C, __half* Ch, int M, int N, int K) {
    dim3 grid((N + 127) / 128, M / 128);
    gemm_fp16_kernel<<<grid, 256, GEMM_SMEM>>>(A, WT, bias, R, C, Ch, M, N, K);
}

extern "C" void kernel_launch(void* const* d_in, const int* in_sizes, int n_in,
                              void* d_out, int out_size) {
    const float* query = (const float*)d_in[0];
    const float* refp  = (const float*)d_in[1];
    const float* feat  = (const float*)d_in[2];
    const float* qn_w = (const float*)d_in[7];
    const float* qn_b = (const float*)d_in[8];
    const float* fn_w = (const float*)d_in[9];
    const float* fn_b = (const float*)d_in[10];
    const float* so_w = (const float*)d_in[11];
    const float* so_b = (const float*)d_in[12];
    const float* aw_w = (const float*)d_in[13];
    const float* aw_b = (const float*)d_in[14];
    const float* vp_w = (const float*)d_in[15];
    const float* vp_b = (const float*)d_in[16];
    const float* op_w = (const float*)d_in[17];
    const float* op_b = (const float*)d_in[18];
    const float* ffn_w = (const float*)d_in[19];
    const float* ffn_b = (const float*)d_in[20];
    const float* fc1_w = (const float*)d_in[21];
    const float* fc1_b = (const float*)d_in[22];
    const float* dw_w  = (const float*)d_in[23];
    const float* dw_b  = (const float*)d_in[24];
    const float* fc2_w = (const float*)d_in[25];
    const float* fc2_b = (const float*)d_in[26];
    float* out = (float*)d_out;

    __half *p_qln16, *p_fln16, *p_val16, *p_attn16, *p_x1h, *p_x2h;
    __half *p_vpT, *p_opT, *p_fc1T, *p_fc2T, *p_w72T;
    float *p_oa, *p_q2, *p_b72;
    cudaGetSymbolAddress((void**)&p_qln16,  g_qln16);
    cudaGetSymbolAddress((void**)&p_fln16,  g_fln16);
    cudaGetSymbolAddress((void**)&p_val16,  g_val16);
    cudaGetSymbolAddress((void**)&p_attn16, g_attn16);
    cudaGetSymbolAddress((void**)&p_x1h,    g_x1h);
    cudaGetSymbolAddress((void**)&p_x2h,    g_x2h);
    cudaGetSymbolAddress((void**)&p_vpT,    g_vpT16);
    cudaGetSymbolAddress((void**)&p_opT,    g_opT16);
    cudaGetSymbolAddress((void**)&p_fc1T,   g_fc1T16);
    cudaGetSymbolAddress((void**)&p_fc2T,   g_fc2T16);
    cudaGetSymbolAddress((void**)&p_w72T,   g_w72T16);
    cudaGetSymbolAddress((void**)&p_oa,     g_oa);
    cudaGetSymbolAddress((void**)&p_q2,     g_q2);
    cudaGetSymbolAddress((void**)&p_b72,    g_b72);

    cudaFuncSetAttribute(gemm_fp16_kernel, cudaFuncAttributeMaxDynamicSharedMemorySize, GEMM_SMEM);

    // 0. weight prep: transpose to [N][K] + fp16 convert
    transpose_h_kernel<<<dim3(24, 24), dim3(32, 8)>>>(vp_w,  p_vpT,  CC, CC);
    transpose_h_kernel<<<dim3(24, 24), dim3(32, 8)>>>(op_w,  p_opT,  CC, CC);
    transpose_h_kernel<<<dim3(6, 24),  dim3(32, 8)>>>(fc1_w, p_fc1T, CC, HID);
    transpose_h_kernel<<<dim3(24, 6),  dim3(32, 8)>>>(fc2_w, p_fc2T, HID, CC);
    pack72_kernel<<<(NOA*CC + 255)/256, 256>>>(so_w, so_b, aw_w, aw_b, p_w72T, p_b72);

    // 1. LayerNorms (fp32 in -> fp16 out)
    ln_kernel<<<MQ, 192>>>(query, qn_w, qn_b, p_qln16);
    ln_kernel<<<MF, 192>>>(feat,  fn_w, fn_b, p_fln16);

    // 2. value = f_ln @ vp_w + vp_b   (32768 x 768 x 768), half output
    launch_gemm(p_fln16, p_vpT, vp_b, nullptr, nullptr, p_val16, MF, CC, CC);

    // 3. fused sampling-offset + attn-logit projection (24576 x 72 x 768)
    launch_gemm(p_qln16, p_w72T, p_b72, nullptr, p_oa, nullptr, MQ, NOA, CC);

    // 4. softmax + bilinear sample + head-reduce (half in/out)
    sample_kernel<<<MQ, 192>>>(refp, p_attn16);

    // 5. output projection + residual -> q2 fp32   (24576 x 768 x 768)
    launch_gemm(p_attn16, p_opT, op_b, query, p_q2, nullptr, MQ, CC, CC);

    // 6. ConvFFN (fc1 -> half, dwconv half->half, fc2 + residual -> out)
    ln_kernel<<<MQ, 192>>>(p_q2, ffn_w, ffn_b, p_qln16);
    launch_gemm(p_qln16, p_fc1T, fc1_b, nullptr, nullptr, p_x1h, MQ, HID, CC);
    dwconv_gelu_kernel<<<MQ, HID>>>(p_x1h, dw_w, dw_b, p_x2h);
    launch_gemm(p_x2h, p_fc2T, fc2_b, p_q2, out, nullptr, MQ, CC, HID);
}